// round 11
// baseline (speedup 1.0000x reference)
#include <cuda_runtime.h>

// ---------------- problem constants ----------------
#define NB 8
#define NP 2000
#define NC 81
#define NPC 80                    // classes excluding background
#define NM (NP*NPC)               // 160000 candidates per image
#define NROWS (NB*NP)             // 16000 proposal rows
#define KPRE 2048
#define SORTCAP 8192
#define NDET 100
#define W_IMG 1333.0f
#define H_IMG 800.0f
#define SCORE_T 0.05f
#define NMS_T 0.5f
#define BBOX_CLIP 4.135166556742356f   // log(1000/16)
#define FASTK 256                 // fast-path prefix size
#define CBLK 8                    // compaction blocks per image

typedef unsigned long long ull;

// ---------------- device scratch (static, no allocs) ----------------
static __device__ int  g_ncand[NB][1024];      // padded 4KB apart
static __device__ int  g_nsel[NB][1024];       // padded 4KB apart
static __device__ int  g_hist[NB][16384];      // per-image score-bit histogram
static __device__ ull  g_keys[NB][NM];         // ~10.2 MB
static __device__ ull  g_sel[NB][FASTK];       // fast-path selected keys (unordered)

// ---------------- helpers ----------------
__device__ __forceinline__ float4 decode_box(float4 pr, float r0, float r1, float r2, float r3) {
    float w  = pr.z - pr.x, h  = pr.w - pr.y;
    float cx = pr.x + 0.5f * w, cy = pr.y + 0.5f * h;
    float dx = r0 / 10.0f, dy = r1 / 10.0f;
    float dw = fminf(r2 / 5.0f, BBOX_CLIP);
    float dh = fminf(r3 / 5.0f, BBOX_CLIP);
    float pcx = dx * w + cx, pcy = dy * h + cy;
    float pw  = expf(dw) * w, ph = expf(dh) * h;
    float x1 = pcx - 0.5f * pw, y1 = pcy - 0.5f * ph;
    float x2 = pcx + 0.5f * pw, y2 = pcy + 0.5f * ph;
    x1 = fminf(fmaxf(x1, 0.0f), W_IMG);
    x2 = fminf(fmaxf(x2, 0.0f), W_IMG);
    y1 = fminf(fmaxf(y1, 0.0f), H_IMG);
    y2 = fminf(fmaxf(y2, 0.0f), H_IMG);
    return make_float4(x1, y1, x2, y2);
}

__device__ __forceinline__ bool iou_gt(float4 a, float4 b) {
    float aa = fmaxf(a.z - a.x, 0.f) * fmaxf(a.w - a.y, 0.f);
    float ab = fmaxf(b.z - b.x, 0.f) * fmaxf(b.w - b.y, 0.f);
    float ltx = fmaxf(a.x, b.x), lty = fmaxf(a.y, b.y);
    float rbx = fminf(a.z, b.z), rby = fminf(a.w, b.w);
    float iw = fmaxf(rbx - ltx, 0.f), ih = fmaxf(rby - lty, 0.f);
    float inter = iw * ih;
    float uni = aa + ab - inter;
    return inter / fmaxf(uni, 1e-9f) > NMS_T;
}

__device__ __forceinline__ int score_bin(unsigned sb) {
    return min(max((int)((sb - 0x3D000000u) >> 12), 0), 16383);
}

// ---- parallel 3-level cut finder over a (global) histogram ----
__device__ __forceinline__ void find_cut_g(const int* __restrict__ ghist, int LIMIT,
                                           int* coarse, int* ssum,
                                           int* s_cb, int* s_na,
                                           int tid, int warp, int lane) {
    const int4* h4 = (const int4*)(ghist + tid * 16);
    int4 a0 = h4[0], a1 = h4[1], a2 = h4[2], a3 = h4[3];
    int seg = a0.x + a0.y + a0.z + a0.w + a1.x + a1.y + a1.z + a1.w
            + a2.x + a2.y + a2.z + a2.w + a3.x + a3.y + a3.z + a3.w;
    coarse[tid] = seg;
    int ws = seg;
    #pragma unroll
    for (int o = 16; o; o >>= 1) ws += __shfl_xor_sync(0xffffffffu, ws, o);
    if (lane == 0) ssum[warp] = ws;
    __syncthreads();
    if (warp == 0) {
        int suf1 = ssum[lane];
        #pragma unroll
        for (int o = 1; o < 32; o <<= 1) {
            int t = __shfl_down_sync(0xffffffffu, suf1, o);
            if (lane + o < 32) suf1 += t;
        }
        int total = __shfl_sync(0xffffffffu, suf1, 0);
        unsigned m1 = __ballot_sync(0xffffffffu, suf1 > LIMIT);
        if (m1 == 0) {
            if (lane == 0) { *s_cb = -1; *s_na = total; }
        } else {
            int w1 = 31 - __clz(m1);
            int cum0 = (w1 < 31) ? __shfl_sync(0xffffffffu, suf1, w1 + 1) : 0;
            int suf2 = coarse[w1 * 32 + lane];
            #pragma unroll
            for (int o = 1; o < 32; o <<= 1) {
                int t = __shfl_down_sync(0xffffffffu, suf2, o);
                if (lane + o < 32) suf2 += t;
            }
            suf2 += cum0;
            unsigned m2 = __ballot_sync(0xffffffffu, suf2 > LIMIT);
            int t2 = 31 - __clz(m2);
            int cum1 = (t2 < 31) ? __shfl_sync(0xffffffffu, suf2, t2 + 1) : cum0;
            int segi = w1 * 32 + t2;
            int suf3 = (lane < 16) ? ghist[segi * 16 + lane] : 0;
            #pragma unroll
            for (int o = 1; o < 16; o <<= 1) {
                int t = __shfl_down_sync(0xffffffffu, suf3, o);
                if (lane + o < 16) suf3 += t;
            }
            suf3 += cum1;
            unsigned m3 = __ballot_sync(0xffffffffu, (lane < 16) && (suf3 > LIMIT));
            int b3 = 31 - __clz(m3);
            int na = (b3 < 15) ? __shfl_sync(0xffffffffu, suf3, b3 + 1) : cum1;
            if (lane == 0) { *s_cb = segi * 16 + b3; *s_na = na; }
        }
    }
    __syncthreads();
}

// ========= kernel 1: softmax + threshold + decode + compact + global hist =========
// Lane l owns classes {l, l+32, l+64}: the logits loaded for the softmax
// denominator ARE the candidate logits, and the expf values computed for den
// are reused as score numerators (bit-identical to recomputation). No second
// pass, no gate expf/logf; precise fdiv only behind a provably-superset
// FMA prefilter.
__global__ void k_score(const float* __restrict__ logits,
                        const float* __restrict__ reg,
                        const float* __restrict__ props) {
    int gw = (blockIdx.x * blockDim.x + threadIdx.x) >> 5;
    int lane = threadIdx.x & 31;
    if (gw >= NROWS) return;
    int row = gw;
    int b = row / NP;
    int p = row - b * NP;
    const float* lr = logits + (size_t)row * NC;
    bool has2 = lane < (NC - 64);               // lane < 17 -> class lane+64 <= 80
    float v0 = lr[lane];                        // class lane      (candidate if lane>=1)
    float v1 = lr[lane + 32];                   // class lane+32
    float v2 = has2 ? lr[lane + 64] : -1e30f;   // class lane+64
    float mx = fmaxf(v0, fmaxf(v1, v2));
    #pragma unroll
    for (int o = 16; o; o >>= 1) mx = fmaxf(mx, __shfl_xor_sync(0xffffffffu, mx, o));
    float e0 = expf(v0 - mx);
    float e1 = expf(v1 - mx);
    float e2 = has2 ? expf(v2 - mx) : 0.0f;
    float den = e0 + e1 + e2;
    #pragma unroll
    for (int o = 16; o; o >>= 1) den += __shfl_xor_sync(0xffffffffu, den, o);
    float pre = SCORE_T * den * 0.9999f;        // prefilter margin >> few ulp
    float4 pr = ((const float4*)props)[row];
    #pragma unroll
    for (int it = 0; it < 3; it++) {
        float e = (it == 0) ? e0 : (it == 1) ? e1 : e2;
        int c = lane + it * 32;
        bool cand = (it == 0) ? (lane >= 1) : (it == 1) ? true : has2;
        bool pass = false;
        ull key = 0ull;
        unsigned sbv = 0u;
        if (cand && e > pre) {
            float score = e / den;              // exact reference expression
            if (score > SCORE_T) {
                float4 rg = *(const float4*)(reg + (size_t)row * (NC * 4) + c * 4);
                float4 bx = decode_box(pr, rg.x, rg.y, rg.z, rg.w);
                if ((bx.z - bx.x) >= 0.01f && (bx.w - bx.y) >= 0.01f) {
                    pass = true;
                    sbv = __float_as_uint(score);
                    key = (((ull)(~sbv)) << 32) | (unsigned int)(p * NPC + (c - 1));
                }
            }
        }
        unsigned mask = __ballot_sync(0xffffffffu, pass);
        if (mask) {
            int leader = __ffs(mask) - 1;
            int basec = 0;
            if (lane == leader) basec = atomicAdd(&g_ncand[b][0], __popc(mask));
            basec = __shfl_sync(0xffffffffu, basec, leader);
            if (pass) {
                int slot = basec + __popc(mask & ((1u << lane) - 1u));
                g_keys[b][slot] = key;
                atomicAdd(&g_hist[b][score_bin(sbv)], 1);
            }
        }
    }
}

// ========= kernel 2: grid-wide fast-path compaction (unordered) =========
__global__ __launch_bounds__(1024, 1)
void k_compact() {
    __shared__ int coarse[1024];
    __shared__ int ssum[32];
    __shared__ int s_cb, s_na;
    int bb = blockIdx.x;
    int b = bb >> 3, s = bb & (CBLK - 1);
    int tid = threadIdx.x, warp = tid >> 5, lane = tid & 31;
    int n = g_ncand[b][0];
    find_cut_g(g_hist[b], FASTK, coarse, ssum, &s_cb, &s_na, tid, warp, lane);
    int cb = s_cb;
    int per = (n + CBLK - 1) / CBLK;
    int lo = s * per, hi = min(n, lo + per);
    int span = hi - lo;
    if (span <= 0) return;
    int nn = (span + 1023) & ~1023;
    for (int i = tid; i < nn; i += 1024) {
        bool act = i < span;
        ull k = act ? g_keys[b][lo + i] : 0ull;
        bool sel = act && (score_bin(~((unsigned)(k >> 32))) > cb);  // exclusive -> true prefix set
        unsigned msk = __ballot_sync(0xffffffffu, sel);
        if (msk) {
            int leader = __ffs(msk) - 1;
            int basec = 0;
            if (lane == leader) basec = atomicAdd(&g_nsel[b][0], __popc(msk));
            basec = __shfl_sync(0xffffffffu, basec, leader);
            if (sel) {
                int o = basec + __popc(msk & ((1u << lane) - 1u));
                if (o < FASTK) g_sel[b][o] = k;
            }
        }
    }
}

// ========= kernel 3: sort + lazy NMS + finalize (8 blocks) =========
// dyn smem: keys[SORTCAP] u64 (64KB) | coarse[1024] int (4KB)
extern __shared__ unsigned char s_raw[];

__global__ __launch_bounds__(1024, 1)
void k_topnms(const float* __restrict__ logits,
              const float* __restrict__ reg,
              const float* __restrict__ props,
              float* __restrict__ out) {
    int b = blockIdx.x, tid = threadIdx.x;
    int warp = tid >> 5, lane = tid & 31;
    ull* keys = (ull*)s_raw;
    int* coarse = (int*)(s_raw + 65536);

    __shared__ int ssum[32];
    __shared__ int s_cb, s_na, s_outc;
    __shared__ float4 wbox[64];
    __shared__ int    wlab[64];
    __shared__ ull    inrow[64];
    __shared__ ull    s_sup;
    __shared__ ull    kw[32];
    __shared__ int    s_kcount, s_stop;
    __shared__ int    npre[33];
    __shared__ float4 kbox[256];
    __shared__ unsigned char klab[256];
    __shared__ float  kscore[256];

    // ---- greedy lazy NMS over keys[0..ntop) ----
    auto run_nms = [&](int ntop) -> int {
        if (tid == 0) { s_kcount = 0; s_stop = 0; }
        if (tid < 32) kw[tid] = 0ull;
        __syncthreads();
        for (int w = 0; w * 64 < ntop; w++) {
            int base = w * 64;
            int nword = min(64, ntop - base);
            if (tid < 64) {
                if (tid < nword) {
                    ull key = keys[base + tid];
                    unsigned m = (unsigned)key;
                    int p = m / NPC, cm = m - p * NPC, c = cm + 1;
                    int row = b * NP + p;
                    float4 rg = *(const float4*)(reg + (size_t)row * (NC * 4) + c * 4);
                    float4 pr = ((const float4*)props)[row];
                    wbox[tid] = decode_box(pr, rg.x, rg.y, rg.z, rg.w);
                    wlab[tid] = c;
                } else wlab[tid] = -1;
                inrow[tid] = 0ull;
            }
            if (tid == 64) s_sup = 0ull;
            __syncthreads();
            int K = s_kcount;
            for (int idx = tid; idx < K * nword; idx += 1024) {
                int i = idx / nword, j = idx - i * nword;
                if ((int)klab[i] == wlab[j] && iou_gt(kbox[i], wbox[j]))
                    atomicOr(&s_sup, 1ull << j);
            }
            for (int idx = tid; idx < 4096; idx += 1024) {
                int i = idx >> 6, j = idx & 63;
                if (j > i && j < nword && wlab[i] == wlab[j] && iou_gt(wbox[i], wbox[j]))
                    atomicOr(&inrow[i], 1ull << j);
            }
            __syncthreads();
            if (warp == 0) {
                ull pend = ((nword == 64) ? ~0ull : ((1ull << nword) - 1ull)) & ~s_sup;
                ull r0 = inrow[lane], r1 = inrow[lane + 32];
                ull kept = 0ull;
                while (pend) {
                    unsigned c0 = __ballot_sync(0xffffffffu,
                        ((pend >> lane) & 1ull) && (r0 & pend));
                    unsigned c1 = __ballot_sync(0xffffffffu,
                        ((pend >> (lane + 32)) & 1ull) && (r1 & pend));
                    ull conf = (ull)c0 | ((ull)c1 << 32);
                    if (!conf) { kept |= pend; break; }
                    int fc = __ffsll((long long)conf) - 1;
                    ull upto = (fc == 63) ? ~0ull : ((2ull << fc) - 1ull);
                    kept |= pend & upto;
                    pend &= ~upto;
                    pend &= ~inrow[fc];
                }
                int K0 = s_kcount;
                #pragma unroll
                for (int half = 0; half < 2; half++) {
                    int bpos = lane + half * 32;
                    if ((kept >> bpos) & 1ull) {
                        ull below = bpos ? ((1ull << bpos) - 1ull) : 0ull;
                        int pos = K0 + __popcll(kept & below);
                        if (pos < 256) {
                            kbox[pos] = wbox[bpos];
                            klab[pos] = (unsigned char)wlab[bpos];
                            kscore[pos] = __uint_as_float(~((unsigned)(keys[base + bpos] >> 32)));
                        }
                    }
                }
                if (lane == 0) {
                    kw[w] = kept;
                    s_kcount = K0 + __popcll(kept);
                    if (s_kcount >= NDET) s_stop = 1;
                }
            }
            __syncthreads();
            if (s_stop) break;                // uniform
        }
        return s_kcount;
    };

    // ================= fast path: pre-selected exact prefix set (na <= FASTK) ========
    int na = min(g_nsel[b][0], FASTK);
    // hybrid bitonic sort of FASTK=256 (6 smem stages; j<32 via shfl)
    {
        ull v = (tid < na) ? g_sel[b][tid] : ~0ull;
        for (int k = 2; k <= FASTK; k <<= 1) {
            for (int j = k >> 1; j; j >>= 1) {
                ull o;
                if (j >= 32) {
                    if (tid < FASTK) keys[tid] = v;
                    __syncthreads();
                    o = (tid < FASTK) ? keys[tid ^ j] : v;
                    __syncthreads();
                } else {
                    o = __shfl_xor_sync(0xffffffffu, v, j);
                }
                bool up = ((tid & k) == 0);
                bool lower = ((tid & j) == 0);
                ull mn = v < o ? v : o, mx = v < o ? o : v;
                if (tid < FASTK) v = (lower == up) ? mn : mx;
            }
        }
        if (tid < FASTK) keys[tid] = v;
        __syncthreads();
    }

    int kcount = run_nms(na);
    int ntop = na;

    // ================= fallback: exact top-2048 (rare; single-block slow path) ======
    if (kcount < NDET) {
        int n = g_ncand[b][0];
        find_cut_g(g_hist[b], KPRE, coarse, ssum, &s_cb, &s_na, tid, warp, lane);
        int cb2 = max(s_cb, 0);
        if (tid == 0) s_outc = 0;
        __syncthreads();
        int nn = (n + 1023) & ~1023;
        for (int i = tid; i < nn; i += 1024) {
            bool act = i < n;
            ull k = act ? g_keys[b][i] : 0ull;
            bool sel = act && (score_bin(~((unsigned)(k >> 32))) >= cb2);  // superset
            unsigned msk = __ballot_sync(0xffffffffu, sel);
            if (msk) {
                int leader = __ffs(msk) - 1;
                int basec = 0;
                if (lane == leader) basec = atomicAdd(&s_outc, __popc(msk));
                basec = __shfl_sync(0xffffffffu, basec, leader);
                if (sel) {
                    int o = basec + __popc(msk & ((1u << lane) - 1u));
                    if (o < SORTCAP) keys[o] = k;
                }
            }
        }
        __syncthreads();
        int nsel = min(s_outc, SORTCAP);
        int npad = KPRE;
        while (npad < nsel) npad <<= 1;
        for (int i = tid; i < npad; i += 1024) if (i >= nsel) keys[i] = ~0ull;
        __syncthreads();
        for (int k = 2; k <= npad; k <<= 1) {
            for (int j = k >> 1; j; j >>= 1) {
                for (int t = tid; t < npad; t += 1024) {
                    int x = t ^ j;
                    if (x > t) {
                        ull a = keys[t], c = keys[x];
                        bool up = ((t & k) == 0);
                        if ((a > c) == up) { keys[t] = c; keys[x] = a; }
                    }
                }
                __syncthreads();
            }
        }
        ntop = min(nsel, KPRE);
        kcount = run_nms(ntop);
    }

    // ================= outputs =================
    const int OFF_S = NB * NDET * 4;
    const int OFF_L = NB * NDET * 5;
    const int OFF_V = NB * NDET * 6;
    int nk = min(kcount, NDET);
    for (int r = tid; r < nk; r += 1024) {
        int o = b * NDET + r;
        float4 bx = kbox[r];
        out[o * 4 + 0] = bx.x; out[o * 4 + 1] = bx.y;
        out[o * 4 + 2] = bx.z; out[o * 4 + 3] = bx.w;
        out[OFF_S + o] = kscore[r];
        out[OFF_L + o] = (float)klab[r];
        out[OFF_V + o] = 1.0f;
    }
    if (kcount < NDET) {                      // NMS exhausted -> kw complete
        if (tid == 0) {
            int cn = 0;
            for (int ww = 0; ww < 32; ww++) {
                npre[ww] = cn;
                int bb = ww * 64;
                ull validw = (ntop >= bb + 64) ? ~0ull
                    : (ntop <= bb ? 0ull : ((1ull << (ntop - bb)) - 1ull));
                cn += __popcll(validw & ~kw[ww]);
            }
            npre[32] = cn;
        }
        __syncthreads();
        for (int pos = tid; pos < ntop; pos += 1024) {
            int ww = pos >> 6, bit = pos & 63;
            if ((kw[ww] >> bit) & 1ull) continue;
            ull below = bit ? ((1ull << bit) - 1ull) : 0ull;
            int rank = kcount + npre[ww] + __popcll((~kw[ww]) & below);
            if (rank < NDET) {
                ull key = keys[pos];
                unsigned m = (unsigned)key;
                int p = m / NPC, cm = m - p * NPC, c = cm + 1;
                int row = b * NP + p;
                float4 rg = *(const float4*)(reg + (size_t)row * (NC * 4) + c * 4);
                float4 pr = ((const float4*)props)[row];
                float4 bx = decode_box(pr, rg.x, rg.y, rg.z, rg.w);
                int o = b * NDET + rank;
                out[o * 4 + 0] = bx.x; out[o * 4 + 1] = bx.y;
                out[o * 4 + 2] = bx.z; out[o * 4 + 3] = bx.w;
                out[OFF_S + o] = -1.0f;
                out[OFF_L + o] = (float)c;
                out[OFF_V + o] = 0.0f;
            }
        }
        __syncthreads();
        // pathological filler (ntop < 100): reference top_k -1 tie order
        if (tid == 0 && ntop < NDET) {
            int slot = ntop;
            for (int m = 0; m < NM && slot < NDET; m++) {
                int p = m / NPC, cm = m - p * NPC, c = cm + 1;
                int row = b * NP + p;
                const float* lr = logits + (size_t)row * NC;
                float mx = -1e30f;
                for (int q = 0; q < NC; q++) mx = fmaxf(mx, lr[q]);
                float den = 0.f;
                for (int q = 0; q < NC; q++) den += expf(lr[q] - mx);
                float score = expf(lr[c] - mx) / den;
                const float* rg = reg + (size_t)row * (NC * 4) + c * 4;
                float4 pr = ((const float4*)props)[row];
                float4 bx = decode_box(pr, rg[0], rg[1], rg[2], rg[3]);
                bool valid = (score > SCORE_T) && ((bx.z - bx.x) >= 0.01f)
                           && ((bx.w - bx.y) >= 0.01f);
                if (!valid) {
                    int o = b * NDET + slot;
                    out[o * 4 + 0] = bx.x; out[o * 4 + 1] = bx.y;
                    out[o * 4 + 2] = bx.z; out[o * 4 + 3] = bx.w;
                    out[OFF_S + o] = -1.0f;
                    out[OFF_L + o] = (float)c;
                    out[OFF_V + o] = 0.0f;
                    slot++;
                }
            }
        }
    }
    // ---- reset scratch so every execution ends zeroed (graph-replay safe) ----
    __syncthreads();
    {
        int4* hz = (int4*)g_hist[b];
        int4 z = make_int4(0, 0, 0, 0);
        #pragma unroll
        for (int i = 0; i < 4; i++) hz[tid + i * 1024] = z;
    }
    if (tid == 0) { g_ncand[b][0] = 0; g_nsel[b][0] = 0; }
}

// ---------------- launch ----------------
extern "C" void kernel_launch(void* const* d_in, const int* in_sizes, int n_in,
                              void* d_out, int out_size) {
    const float* logits = nullptr;
    const float* reg    = nullptr;
    const float* props  = nullptr;
    for (int i = 0; i < n_in; i++) {
        if      (in_sizes[i] == NROWS * NC)     logits = (const float*)d_in[i];
        else if (in_sizes[i] == NROWS * NC * 4) reg    = (const float*)d_in[i];
        else if (in_sizes[i] == NROWS * 4)      props  = (const float*)d_in[i];
    }
    float* out = (float*)d_out;

    static int s_attr_done = 0;
    if (!s_attr_done) {
        cudaFuncSetAttribute(k_topnms, cudaFuncAttributeMaxDynamicSharedMemorySize, 69632);
        s_attr_done = 1;
    }

    k_score<<<(NROWS * 32 + 255) / 256, 256>>>(logits, reg, props);
    k_compact<<<NB * CBLK, 1024>>>();
    k_topnms<<<NB, 1024, 69632>>>(logits, reg, props, out);
}

// round 12
// speedup vs baseline: 1.0077x; 1.0077x over previous
#include <cuda_runtime.h>

// ---------------- problem constants ----------------
#define NB 8
#define NP 2000
#define NC 81
#define NPC 80                    // classes excluding background
#define NM (NP*NPC)               // 160000 candidates per image
#define NROWS (NB*NP)             // 16000 proposal rows
#define KPRE 2048
#define SORTCAP 8192
#define NDET 100
#define W_IMG 1333.0f
#define H_IMG 800.0f
#define SCORE_T 0.05f
#define NMS_T 0.5f
#define BBOX_CLIP 4.135166556742356f   // log(1000/16)
#define FASTK 256                 // fast-path prefix size
#define CBLK 8                    // compaction blocks per image

typedef unsigned long long ull;

// ---------------- device scratch (static, no allocs) ----------------
static __device__ int  g_ncand[NB][1024];      // padded 4KB apart
static __device__ int  g_nsel[NB][1024];       // padded 4KB apart
static __device__ int  g_hist[NB][16384];      // per-image score-bit histogram
static __device__ ull  g_keys[NB][NM];         // ~10.2 MB
static __device__ ull  g_sel[NB][FASTK];       // fast-path selected keys (unordered)

// ---------------- helpers ----------------
__device__ __forceinline__ float4 decode_box(float4 pr, float r0, float r1, float r2, float r3) {
    float w  = pr.z - pr.x, h  = pr.w - pr.y;
    float cx = pr.x + 0.5f * w, cy = pr.y + 0.5f * h;
    float dx = r0 / 10.0f, dy = r1 / 10.0f;
    float dw = fminf(r2 / 5.0f, BBOX_CLIP);
    float dh = fminf(r3 / 5.0f, BBOX_CLIP);
    float pcx = dx * w + cx, pcy = dy * h + cy;
    float pw  = expf(dw) * w, ph = expf(dh) * h;
    float x1 = pcx - 0.5f * pw, y1 = pcy - 0.5f * ph;
    float x2 = pcx + 0.5f * pw, y2 = pcy + 0.5f * ph;
    x1 = fminf(fmaxf(x1, 0.0f), W_IMG);
    x2 = fminf(fmaxf(x2, 0.0f), W_IMG);
    y1 = fminf(fmaxf(y1, 0.0f), H_IMG);
    y2 = fminf(fmaxf(y2, 0.0f), H_IMG);
    return make_float4(x1, y1, x2, y2);
}

__device__ __forceinline__ bool iou_gt(float4 a, float4 b) {
    float aa = fmaxf(a.z - a.x, 0.f) * fmaxf(a.w - a.y, 0.f);
    float ab = fmaxf(b.z - b.x, 0.f) * fmaxf(b.w - b.y, 0.f);
    float ltx = fmaxf(a.x, b.x), lty = fmaxf(a.y, b.y);
    float rbx = fminf(a.z, b.z), rby = fminf(a.w, b.w);
    float iw = fmaxf(rbx - ltx, 0.f), ih = fmaxf(rby - lty, 0.f);
    float inter = iw * ih;
    float uni = aa + ab - inter;
    return inter / fmaxf(uni, 1e-9f) > NMS_T;
}

__device__ __forceinline__ int score_bin(unsigned sb) {
    return min(max((int)((sb - 0x3D000000u) >> 12), 0), 16383);
}

// ---- parallel 3-level cut finder over a (global) histogram ----
__device__ __forceinline__ void find_cut_g(const int* __restrict__ ghist, int LIMIT,
                                           int* coarse, int* ssum,
                                           int* s_cb, int* s_na,
                                           int tid, int warp, int lane) {
    const int4* h4 = (const int4*)(ghist + tid * 16);
    int4 a0 = h4[0], a1 = h4[1], a2 = h4[2], a3 = h4[3];
    int seg = a0.x + a0.y + a0.z + a0.w + a1.x + a1.y + a1.z + a1.w
            + a2.x + a2.y + a2.z + a2.w + a3.x + a3.y + a3.z + a3.w;
    coarse[tid] = seg;
    int ws = seg;
    #pragma unroll
    for (int o = 16; o; o >>= 1) ws += __shfl_xor_sync(0xffffffffu, ws, o);
    if (lane == 0) ssum[warp] = ws;
    __syncthreads();
    if (warp == 0) {
        int suf1 = ssum[lane];
        #pragma unroll
        for (int o = 1; o < 32; o <<= 1) {
            int t = __shfl_down_sync(0xffffffffu, suf1, o);
            if (lane + o < 32) suf1 += t;
        }
        int total = __shfl_sync(0xffffffffu, suf1, 0);
        unsigned m1 = __ballot_sync(0xffffffffu, suf1 > LIMIT);
        if (m1 == 0) {
            if (lane == 0) { *s_cb = -1; *s_na = total; }
        } else {
            int w1 = 31 - __clz(m1);
            int cum0 = (w1 < 31) ? __shfl_sync(0xffffffffu, suf1, w1 + 1) : 0;
            int suf2 = coarse[w1 * 32 + lane];
            #pragma unroll
            for (int o = 1; o < 32; o <<= 1) {
                int t = __shfl_down_sync(0xffffffffu, suf2, o);
                if (lane + o < 32) suf2 += t;
            }
            suf2 += cum0;
            unsigned m2 = __ballot_sync(0xffffffffu, suf2 > LIMIT);
            int t2 = 31 - __clz(m2);
            int cum1 = (t2 < 31) ? __shfl_sync(0xffffffffu, suf2, t2 + 1) : cum0;
            int segi = w1 * 32 + t2;
            int suf3 = (lane < 16) ? ghist[segi * 16 + lane] : 0;
            #pragma unroll
            for (int o = 1; o < 16; o <<= 1) {
                int t = __shfl_down_sync(0xffffffffu, suf3, o);
                if (lane + o < 16) suf3 += t;
            }
            suf3 += cum1;
            unsigned m3 = __ballot_sync(0xffffffffu, (lane < 16) && (suf3 > LIMIT));
            int b3 = 31 - __clz(m3);
            int na = (b3 < 15) ? __shfl_sync(0xffffffffu, suf3, b3 + 1) : cum1;
            if (lane == 0) { *s_cb = segi * 16 + b3; *s_na = na; }
        }
    }
    __syncthreads();
}

// ========= kernel 1: softmax + threshold + decode + compact + global hist =========
// TWO rows per warp: 6 independent logit loads in flight, interleaved shfl
// reduction trees (ILP=2 on the serial chain), one aggregated atomic ticket
// per iteration covering both rows. Row pairs never cross images (NP even).
__global__ void k_score(const float* __restrict__ logits,
                        const float* __restrict__ reg,
                        const float* __restrict__ props) {
    int gw = (blockIdx.x * blockDim.x + threadIdx.x) >> 5;   // pair index
    int lane = threadIdx.x & 31;
    if (gw >= NROWS / 2) return;
    int row0 = gw * 2, row1 = row0 + 1;
    int b = row0 / NP;
    int p0 = row0 - b * NP, p1 = p0 + 1;
    const float* lr0 = logits + (size_t)row0 * NC;
    const float* lr1 = logits + (size_t)row1 * NC;
    bool has2 = lane < (NC - 64);               // lane < 17
    // 6 independent loads issued before first dependent use
    float a0 = lr0[lane],      b0 = lr1[lane];
    float a1 = lr0[lane + 32], b1 = lr1[lane + 32];
    float a2 = has2 ? lr0[lane + 64] : -1e30f;
    float b2 = has2 ? lr1[lane + 64] : -1e30f;
    float mxa = fmaxf(a0, fmaxf(a1, a2));
    float mxb = fmaxf(b0, fmaxf(b1, b2));
    #pragma unroll
    for (int o = 16; o; o >>= 1) {
        mxa = fmaxf(mxa, __shfl_xor_sync(0xffffffffu, mxa, o));
        mxb = fmaxf(mxb, __shfl_xor_sync(0xffffffffu, mxb, o));
    }
    float ea0 = expf(a0 - mxa), eb0 = expf(b0 - mxb);
    float ea1 = expf(a1 - mxa), eb1 = expf(b1 - mxb);
    float ea2 = has2 ? expf(a2 - mxa) : 0.0f;
    float eb2 = has2 ? expf(b2 - mxb) : 0.0f;
    float dena = ea0 + ea1 + ea2;
    float denb = eb0 + eb1 + eb2;
    #pragma unroll
    for (int o = 16; o; o >>= 1) {
        dena += __shfl_xor_sync(0xffffffffu, dena, o);
        denb += __shfl_xor_sync(0xffffffffu, denb, o);
    }
    float prea = SCORE_T * dena * 0.9999f;
    float preb = SCORE_T * denb * 0.9999f;
    float4 pra = ((const float4*)props)[row0];
    float4 prb = ((const float4*)props)[row1];
    #pragma unroll
    for (int it = 0; it < 3; it++) {
        int c = lane + it * 32;
        bool cand = (it == 0) ? (lane >= 1) : (it == 1) ? true : has2;
        float ea = (it == 0) ? ea0 : (it == 1) ? ea1 : ea2;
        float eb = (it == 0) ? eb0 : (it == 1) ? eb1 : eb2;
        bool pass_a = false, pass_b = false;
        ull key_a = 0ull, key_b = 0ull;
        unsigned sb_a = 0u, sb_b = 0u;
        if (cand && ea > prea) {
            float score = ea / dena;            // exact reference expression
            if (score > SCORE_T) {
                float4 rg = *(const float4*)(reg + (size_t)row0 * (NC * 4) + c * 4);
                float4 bx = decode_box(pra, rg.x, rg.y, rg.z, rg.w);
                if ((bx.z - bx.x) >= 0.01f && (bx.w - bx.y) >= 0.01f) {
                    pass_a = true;
                    sb_a = __float_as_uint(score);
                    key_a = (((ull)(~sb_a)) << 32) | (unsigned int)(p0 * NPC + (c - 1));
                }
            }
        }
        if (cand && eb > preb) {
            float score = eb / denb;
            if (score > SCORE_T) {
                float4 rg = *(const float4*)(reg + (size_t)row1 * (NC * 4) + c * 4);
                float4 bx = decode_box(prb, rg.x, rg.y, rg.z, rg.w);
                if ((bx.z - bx.x) >= 0.01f && (bx.w - bx.y) >= 0.01f) {
                    pass_b = true;
                    sb_b = __float_as_uint(score);
                    key_b = (((ull)(~sb_b)) << 32) | (unsigned int)(p1 * NPC + (c - 1));
                }
            }
        }
        unsigned ma = __ballot_sync(0xffffffffu, pass_a);
        unsigned mb = __ballot_sync(0xffffffffu, pass_b);
        int tot = __popc(ma) + __popc(mb);
        if (tot) {
            int basec = 0;
            if (lane == 0) basec = atomicAdd(&g_ncand[b][0], tot);
            basec = __shfl_sync(0xffffffffu, basec, 0);
            unsigned below = (1u << lane) - 1u;
            if (pass_a) {
                int slot = basec + __popc(ma & below);
                g_keys[b][slot] = key_a;
                atomicAdd(&g_hist[b][score_bin(sb_a)], 1);
            }
            if (pass_b) {
                int slot = basec + __popc(ma) + __popc(mb & below);
                g_keys[b][slot] = key_b;
                atomicAdd(&g_hist[b][score_bin(sb_b)], 1);
            }
        }
    }
}

// ========= kernel 2: grid-wide fast-path compaction (unordered) =========
__global__ __launch_bounds__(1024, 1)
void k_compact() {
    __shared__ int coarse[1024];
    __shared__ int ssum[32];
    __shared__ int s_cb, s_na;
    int bb = blockIdx.x;
    int b = bb >> 3, s = bb & (CBLK - 1);
    int tid = threadIdx.x, warp = tid >> 5, lane = tid & 31;
    int n = g_ncand[b][0];
    find_cut_g(g_hist[b], FASTK, coarse, ssum, &s_cb, &s_na, tid, warp, lane);
    int cb = s_cb;
    int per = (n + CBLK - 1) / CBLK;
    int lo = s * per, hi = min(n, lo + per);
    int span = hi - lo;
    if (span <= 0) return;
    int nn = (span + 1023) & ~1023;
    for (int i = tid; i < nn; i += 1024) {
        bool act = i < span;
        ull k = act ? g_keys[b][lo + i] : 0ull;
        bool sel = act && (score_bin(~((unsigned)(k >> 32))) > cb);  // exclusive -> true prefix set
        unsigned msk = __ballot_sync(0xffffffffu, sel);
        if (msk) {
            int leader = __ffs(msk) - 1;
            int basec = 0;
            if (lane == leader) basec = atomicAdd(&g_nsel[b][0], __popc(msk));
            basec = __shfl_sync(0xffffffffu, basec, leader);
            if (sel) {
                int o = basec + __popc(msk & ((1u << lane) - 1u));
                if (o < FASTK) g_sel[b][o] = k;
            }
        }
    }
}

// ========= kernel 3: sort + lazy NMS + finalize (8 blocks) =========
// dyn smem: keys[SORTCAP] u64 (64KB) | coarse[1024] int (4KB)
extern __shared__ unsigned char s_raw[];

__global__ __launch_bounds__(1024, 1)
void k_topnms(const float* __restrict__ logits,
              const float* __restrict__ reg,
              const float* __restrict__ props,
              float* __restrict__ out) {
    int b = blockIdx.x, tid = threadIdx.x;
    int warp = tid >> 5, lane = tid & 31;
    ull* keys = (ull*)s_raw;
    int* coarse = (int*)(s_raw + 65536);

    __shared__ int ssum[32];
    __shared__ int s_cb, s_na, s_outc;
    __shared__ float4 wbox[64];
    __shared__ int    wlab[64];
    __shared__ ull    inrow[64];
    __shared__ ull    s_sup;
    __shared__ ull    kw[32];
    __shared__ int    s_kcount, s_stop;
    __shared__ int    npre[33];
    __shared__ float4 kbox[256];
    __shared__ unsigned char klab[256];
    __shared__ float  kscore[256];

    // ---- greedy lazy NMS over keys[0..ntop) ----
    auto run_nms = [&](int ntop) -> int {
        if (tid == 0) { s_kcount = 0; s_stop = 0; }
        if (tid < 32) kw[tid] = 0ull;
        __syncthreads();
        for (int w = 0; w * 64 < ntop; w++) {
            int base = w * 64;
            int nword = min(64, ntop - base);
            if (tid < 64) {
                if (tid < nword) {
                    ull key = keys[base + tid];
                    unsigned m = (unsigned)key;
                    int p = m / NPC, cm = m - p * NPC, c = cm + 1;
                    int row = b * NP + p;
                    float4 rg = *(const float4*)(reg + (size_t)row * (NC * 4) + c * 4);
                    float4 pr = ((const float4*)props)[row];
                    wbox[tid] = decode_box(pr, rg.x, rg.y, rg.z, rg.w);
                    wlab[tid] = c;
                } else wlab[tid] = -1;
                inrow[tid] = 0ull;
            }
            if (tid == 64) s_sup = 0ull;
            __syncthreads();
            int K = s_kcount;
            for (int idx = tid; idx < K * nword; idx += 1024) {
                int i = idx / nword, j = idx - i * nword;
                if ((int)klab[i] == wlab[j] && iou_gt(kbox[i], wbox[j]))
                    atomicOr(&s_sup, 1ull << j);
            }
            for (int idx = tid; idx < 4096; idx += 1024) {
                int i = idx >> 6, j = idx & 63;
                if (j > i && j < nword && wlab[i] == wlab[j] && iou_gt(wbox[i], wbox[j]))
                    atomicOr(&inrow[i], 1ull << j);
            }
            __syncthreads();
            if (warp == 0) {
                ull pend = ((nword == 64) ? ~0ull : ((1ull << nword) - 1ull)) & ~s_sup;
                ull r0 = inrow[lane], r1 = inrow[lane + 32];
                ull kept = 0ull;
                while (pend) {
                    unsigned c0 = __ballot_sync(0xffffffffu,
                        ((pend >> lane) & 1ull) && (r0 & pend));
                    unsigned c1 = __ballot_sync(0xffffffffu,
                        ((pend >> (lane + 32)) & 1ull) && (r1 & pend));
                    ull conf = (ull)c0 | ((ull)c1 << 32);
                    if (!conf) { kept |= pend; break; }
                    int fc = __ffsll((long long)conf) - 1;
                    ull upto = (fc == 63) ? ~0ull : ((2ull << fc) - 1ull);
                    kept |= pend & upto;
                    pend &= ~upto;
                    pend &= ~inrow[fc];
                }
                int K0 = s_kcount;
                #pragma unroll
                for (int half = 0; half < 2; half++) {
                    int bpos = lane + half * 32;
                    if ((kept >> bpos) & 1ull) {
                        ull below = bpos ? ((1ull << bpos) - 1ull) : 0ull;
                        int pos = K0 + __popcll(kept & below);
                        if (pos < 256) {
                            kbox[pos] = wbox[bpos];
                            klab[pos] = (unsigned char)wlab[bpos];
                            kscore[pos] = __uint_as_float(~((unsigned)(keys[base + bpos] >> 32)));
                        }
                    }
                }
                if (lane == 0) {
                    kw[w] = kept;
                    s_kcount = K0 + __popcll(kept);
                    if (s_kcount >= NDET) s_stop = 1;
                }
            }
            __syncthreads();
            if (s_stop) break;                // uniform
        }
        return s_kcount;
    };

    // ================= fast path: pre-selected exact prefix set (na <= FASTK) ========
    int na = min(g_nsel[b][0], FASTK);
    // hybrid bitonic sort of FASTK=256 (6 smem stages; j<32 via shfl)
    {
        ull v = (tid < na) ? g_sel[b][tid] : ~0ull;
        for (int k = 2; k <= FASTK; k <<= 1) {
            for (int j = k >> 1; j; j >>= 1) {
                ull o;
                if (j >= 32) {
                    if (tid < FASTK) keys[tid] = v;
                    __syncthreads();
                    o = (tid < FASTK) ? keys[tid ^ j] : v;
                    __syncthreads();
                } else {
                    o = __shfl_xor_sync(0xffffffffu, v, j);
                }
                bool up = ((tid & k) == 0);
                bool lower = ((tid & j) == 0);
                ull mn = v < o ? v : o, mx = v < o ? o : v;
                if (tid < FASTK) v = (lower == up) ? mn : mx;
            }
        }
        if (tid < FASTK) keys[tid] = v;
        __syncthreads();
    }

    int kcount = run_nms(na);
    int ntop = na;

    // ================= fallback: exact top-2048 (rare; single-block slow path) ======
    if (kcount < NDET) {
        int n = g_ncand[b][0];
        find_cut_g(g_hist[b], KPRE, coarse, ssum, &s_cb, &s_na, tid, warp, lane);
        int cb2 = max(s_cb, 0);
        if (tid == 0) s_outc = 0;
        __syncthreads();
        int nn = (n + 1023) & ~1023;
        for (int i = tid; i < nn; i += 1024) {
            bool act = i < n;
            ull k = act ? g_keys[b][i] : 0ull;
            bool sel = act && (score_bin(~((unsigned)(k >> 32))) >= cb2);  // superset
            unsigned msk = __ballot_sync(0xffffffffu, sel);
            if (msk) {
                int leader = __ffs(msk) - 1;
                int basec = 0;
                if (lane == leader) basec = atomicAdd(&s_outc, __popc(msk));
                basec = __shfl_sync(0xffffffffu, basec, leader);
                if (sel) {
                    int o = basec + __popc(msk & ((1u << lane) - 1u));
                    if (o < SORTCAP) keys[o] = k;
                }
            }
        }
        __syncthreads();
        int nsel = min(s_outc, SORTCAP);
        int npad = KPRE;
        while (npad < nsel) npad <<= 1;
        for (int i = tid; i < npad; i += 1024) if (i >= nsel) keys[i] = ~0ull;
        __syncthreads();
        for (int k = 2; k <= npad; k <<= 1) {
            for (int j = k >> 1; j; j >>= 1) {
                for (int t = tid; t < npad; t += 1024) {
                    int x = t ^ j;
                    if (x > t) {
                        ull a = keys[t], c = keys[x];
                        bool up = ((t & k) == 0);
                        if ((a > c) == up) { keys[t] = c; keys[x] = a; }
                    }
                }
                __syncthreads();
            }
        }
        ntop = min(nsel, KPRE);
        kcount = run_nms(ntop);
    }

    // ================= outputs =================
    const int OFF_S = NB * NDET * 4;
    const int OFF_L = NB * NDET * 5;
    const int OFF_V = NB * NDET * 6;
    int nk = min(kcount, NDET);
    for (int r = tid; r < nk; r += 1024) {
        int o = b * NDET + r;
        float4 bx = kbox[r];
        out[o * 4 + 0] = bx.x; out[o * 4 + 1] = bx.y;
        out[o * 4 + 2] = bx.z; out[o * 4 + 3] = bx.w;
        out[OFF_S + o] = kscore[r];
        out[OFF_L + o] = (float)klab[r];
        out[OFF_V + o] = 1.0f;
    }
    if (kcount < NDET) {                      // NMS exhausted -> kw complete
        if (tid == 0) {
            int cn = 0;
            for (int ww = 0; ww < 32; ww++) {
                npre[ww] = cn;
                int bb = ww * 64;
                ull validw = (ntop >= bb + 64) ? ~0ull
                    : (ntop <= bb ? 0ull : ((1ull << (ntop - bb)) - 1ull));
                cn += __popcll(validw & ~kw[ww]);
            }
            npre[32] = cn;
        }
        __syncthreads();
        for (int pos = tid; pos < ntop; pos += 1024) {
            int ww = pos >> 6, bit = pos & 63;
            if ((kw[ww] >> bit) & 1ull) continue;
            ull below = bit ? ((1ull << bit) - 1ull) : 0ull;
            int rank = kcount + npre[ww] + __popcll((~kw[ww]) & below);
            if (rank < NDET) {
                ull key = keys[pos];
                unsigned m = (unsigned)key;
                int p = m / NPC, cm = m - p * NPC, c = cm + 1;
                int row = b * NP + p;
                float4 rg = *(const float4*)(reg + (size_t)row * (NC * 4) + c * 4);
                float4 pr = ((const float4*)props)[row];
                float4 bx = decode_box(pr, rg.x, rg.y, rg.z, rg.w);
                int o = b * NDET + rank;
                out[o * 4 + 0] = bx.x; out[o * 4 + 1] = bx.y;
                out[o * 4 + 2] = bx.z; out[o * 4 + 3] = bx.w;
                out[OFF_S + o] = -1.0f;
                out[OFF_L + o] = (float)c;
                out[OFF_V + o] = 0.0f;
            }
        }
        __syncthreads();
        // pathological filler (ntop < 100): reference top_k -1 tie order
        if (tid == 0 && ntop < NDET) {
            int slot = ntop;
            for (int m = 0; m < NM && slot < NDET; m++) {
                int p = m / NPC, cm = m - p * NPC, c = cm + 1;
                int row = b * NP + p;
                const float* lr = logits + (size_t)row * NC;
                float mx = -1e30f;
                for (int q = 0; q < NC; q++) mx = fmaxf(mx, lr[q]);
                float den = 0.f;
                for (int q = 0; q < NC; q++) den += expf(lr[q] - mx);
                float score = expf(lr[c] - mx) / den;
                const float* rg = reg + (size_t)row * (NC * 4) + c * 4;
                float4 pr = ((const float4*)props)[row];
                float4 bx = decode_box(pr, rg[0], rg[1], rg[2], rg[3]);
                bool valid = (score > SCORE_T) && ((bx.z - bx.x) >= 0.01f)
                           && ((bx.w - bx.y) >= 0.01f);
                if (!valid) {
                    int o = b * NDET + slot;
                    out[o * 4 + 0] = bx.x; out[o * 4 + 1] = bx.y;
                    out[o * 4 + 2] = bx.z; out[o * 4 + 3] = bx.w;
                    out[OFF_S + o] = -1.0f;
                    out[OFF_L + o] = (float)c;
                    out[OFF_V + o] = 0.0f;
                    slot++;
                }
            }
        }
    }
    // ---- reset scratch so every execution ends zeroed (graph-replay safe) ----
    __syncthreads();
    {
        int4* hz = (int4*)g_hist[b];
        int4 z = make_int4(0, 0, 0, 0);
        #pragma unroll
        for (int i = 0; i < 4; i++) hz[tid + i * 1024] = z;
    }
    if (tid == 0) { g_ncand[b][0] = 0; g_nsel[b][0] = 0; }
}

// ---------------- launch ----------------
extern "C" void kernel_launch(void* const* d_in, const int* in_sizes, int n_in,
                              void* d_out, int out_size) {
    const float* logits = nullptr;
    const float* reg    = nullptr;
    const float* props  = nullptr;
    for (int i = 0; i < n_in; i++) {
        if      (in_sizes[i] == NROWS * NC)     logits = (const float*)d_in[i];
        else if (in_sizes[i] == NROWS * NC * 4) reg    = (const float*)d_in[i];
        else if (in_sizes[i] == NROWS * 4)      props  = (const float*)d_in[i];
    }
    float* out = (float*)d_out;

    static int s_attr_done = 0;
    if (!s_attr_done) {
        cudaFuncSetAttribute(k_topnms, cudaFuncAttributeMaxDynamicSharedMemorySize, 69632);
        s_attr_done = 1;
    }

    // NROWS/2 row-pairs, one warp each
    k_score<<<((NROWS / 2) * 32 + 255) / 256, 256>>>(logits, reg, props);
    k_compact<<<NB * CBLK, 1024>>>();
    k_topnms<<<NB, 1024, 69632>>>(logits, reg, props, out);
}